// round 14
// baseline (speedup 1.0000x reference)
#include <cuda_runtime.h>
#include <cstddef>

#define N_NODES   50000
#define N_EDGES   800000
#define IN_CH     64
#define HIDDEN    128
#define NUM_GRAPHS 256

typedef unsigned long long u64;

// ---------------- scratch (static device globals; no allocation) ----------------
__device__ float g_agg1[(size_t)N_NODES * IN_CH];    // init = x,  += edge msgs
__device__ float g_agg2[(size_t)N_NODES * HIDDEN];   // init = h1, += edge msgs
__device__ float g_agg3[(size_t)N_NODES * HIDDEN];   // init = h2, += edge msgs
__device__ float g_h1 [(size_t)N_NODES * HIDDEN];
__device__ float g_h2 [(size_t)N_NODES * HIDDEN];
__device__ float g_sums[(size_t)NUM_GRAPHS * HIDDEN];   // zero at static init; div_kernel re-zeroes

// ---------------- packed f32x2 helpers (sm_103a FFMA2) ----------------
__device__ __forceinline__ u64 pack2(float lo, float hi) {
    u64 r;
    asm("mov.b64 %0, {%1, %2};" : "=l"(r) : "r"(__float_as_uint(lo)), "r"(__float_as_uint(hi)));
    return r;
}
__device__ __forceinline__ u64 fma2(u64 a, u64 b, u64 c) {
    u64 d;
    asm("fma.rn.f32x2 %0, %1, %2, %3;" : "=l"(d) : "l"(a), "l"(b), "l"(c));
    return d;
}
__device__ __forceinline__ float2 unpack2(u64 v) {
    unsigned lo, hi;
    asm("mov.b64 {%0, %1}, %2;" : "=r"(lo), "=r"(hi) : "l"(v));
    return make_float2(__uint_as_float(lo), __uint_as_float(hi));
}

// ---------------- vector reductions (sm_90+) ----------------
__device__ __forceinline__ void red_add_v4(float* addr, float4 v) {
    asm volatile("red.global.add.v4.f32 [%0], {%1,%2,%3,%4};"
                 :: "l"(addr), "f"(v.x), "f"(v.y), "f"(v.z), "f"(v.w) : "memory");
}

// ---------------- init kernel ----------------
__global__ void init_agg1_kernel(const float* __restrict__ x) {   // agg1 = x
    const int n4 = N_NODES * IN_CH / 4;
    const float4* x4 = reinterpret_cast<const float4*>(x);
    for (int i = blockIdx.x * blockDim.x + threadIdx.x; i < n4; i += gridDim.x * blockDim.x)
        reinterpret_cast<float4*>(g_agg1)[i] = x4[i];
}

// ---------------- edge kernel D=64: two edges per warp, depth-2 gather pipeline ----------------
__global__ __launch_bounds__(256, 4)
void edge_kernel64(const float* __restrict__ x,
                   const int* __restrict__ ei,
                   const float* __restrict__ ea,
                   const float* __restrict__ We,
                   const float* __restrict__ be,
                   float* __restrict__ agg) {
    __shared__ __align__(16) float4 Wes4[8 * 16];
    __shared__ __align__(16) float4 bes4[16];
    for (int i = threadIdx.x; i < 8 * 16; i += blockDim.x)
        Wes4[i] = reinterpret_cast<const float4*>(We)[i];
    if (threadIdx.x < 16) bes4[threadIdx.x] = reinterpret_cast<const float4*>(be)[threadIdx.x];
    __syncthreads();

    const int lane = threadIdx.x & 31;
    const int half = lane >> 4;
    const int sub  = lane & 15;
    float4 w[8];
#pragma unroll
    for (int k = 0; k < 8; k++) w[k] = Wes4[k * 16 + sub];
    const float4 bj = bes4[sub];

    const int wid = (blockIdx.x * blockDim.x + threadIdx.x) >> 5;
    const int nw  = (gridDim.x * blockDim.x) >> 5;
    int per = (N_EDGES + nw - 1) / nw;
    per = (per + 1) & ~1;
    const int e0 = wid * per;
    const int e1 = (e0 + per < N_EDGES) ? (e0 + per) : N_EDGES;
    if (e0 >= e1) return;

    const int* __restrict__ srcp = ei;
    const int* __restrict__ dstp = ei + N_EDGES;
    const float4* __restrict__ eav = reinterpret_cast<const float4*>(ea);
    const float4* __restrict__ x4 = reinterpret_cast<const float4*>(x);

    const int last = e1 - 1;
    int ic = e0 + half;       if (ic > last) ic = last;
    int in_ = e0 + 2 + half;  if (in_ > last) in_ = last;
    int s_nxt = srcp[in_];
    float4 xv_cur = x4[(size_t)srcp[ic] * 16 + sub];

    for (int e = e0; e < e1; e += 2) {
        float4 xv_nxt = x4[(size_t)s_nxt * 16 + sub];
        int i2 = e + 4 + half; if (i2 > last) i2 = last;
        const int s_n2 = srcp[i2];

        const float4 a0 = eav[(size_t)ic * 2];
        const float4 a1 = eav[(size_t)ic * 2 + 1];
        const int d = dstp[ic];

        float ak[8] = {a0.x, a0.y, a0.z, a0.w, a1.x, a1.y, a1.z, a1.w};
        float4 acc = bj;
#pragma unroll
        for (int k = 0; k < 8; k++) {
            acc.x = fmaf(ak[k], w[k].x, acc.x);
            acc.y = fmaf(ak[k], w[k].y, acc.y);
            acc.z = fmaf(ak[k], w[k].z, acc.z);
            acc.w = fmaf(ak[k], w[k].w, acc.w);
        }
        float4 m;
        m.x = fmaxf(xv_cur.x + acc.x, 0.f);
        m.y = fmaxf(xv_cur.y + acc.y, 0.f);
        m.z = fmaxf(xv_cur.z + acc.z, 0.f);
        m.w = fmaxf(xv_cur.w + acc.w, 0.f);
        if (e + half < e1)
            red_add_v4(&agg[(size_t)d * 64 + sub * 4], m);

        xv_cur = xv_nxt;
        ic = in_; in_ = i2; s_nxt = s_n2;
    }
}

// ---------------- edge kernel D=128: one edge per warp, depth-2 gather pipeline ----------------
__global__ __launch_bounds__(256, 4)
void edge_kernel128(const float* __restrict__ x,
                    const int* __restrict__ ei,
                    const float* __restrict__ ea,
                    const float* __restrict__ We,
                    const float* __restrict__ be,
                    float* __restrict__ agg) {
    __shared__ __align__(16) float4 Wes4[8 * 32];
    __shared__ __align__(16) float4 bes4[32];
    for (int i = threadIdx.x; i < 8 * 32; i += blockDim.x)
        Wes4[i] = reinterpret_cast<const float4*>(We)[i];
    if (threadIdx.x < 32) bes4[threadIdx.x] = reinterpret_cast<const float4*>(be)[threadIdx.x];
    __syncthreads();

    const int lane = threadIdx.x & 31;
    float4 w[8];
#pragma unroll
    for (int k = 0; k < 8; k++) w[k] = Wes4[k * 32 + lane];
    const float4 bj = bes4[lane];

    const int wid = (blockIdx.x * blockDim.x + threadIdx.x) >> 5;
    const int nw  = (gridDim.x * blockDim.x) >> 5;
    const int per = (N_EDGES + nw - 1) / nw;
    const int e0  = wid * per;
    const int e1  = (e0 + per < N_EDGES) ? (e0 + per) : N_EDGES;
    if (e0 >= e1) return;

    const int* __restrict__ srcp = ei;
    const int* __restrict__ dstp = ei + N_EDGES;
    const float4* __restrict__ eav = reinterpret_cast<const float4*>(ea);
    const float4* __restrict__ x4 = reinterpret_cast<const float4*>(x);

    const int last = e1 - 1;
    int s_nxt = srcp[(e0 + 1 <= last) ? e0 + 1 : last];
    float4 xv_cur = x4[(size_t)srcp[e0] * 32 + lane];

    for (int e = e0; e < e1; ++e) {
        float4 xv_nxt = x4[(size_t)s_nxt * 32 + lane];
        const int i2 = (e + 2 <= last) ? e + 2 : last;
        const int s_n2 = srcp[i2];

        const float4 a0 = eav[(size_t)e * 2];
        const float4 a1 = eav[(size_t)e * 2 + 1];
        const int d = dstp[e];

        float ak[8] = {a0.x, a0.y, a0.z, a0.w, a1.x, a1.y, a1.z, a1.w};
        float4 acc = bj;
#pragma unroll
        for (int k = 0; k < 8; k++) {
            acc.x = fmaf(ak[k], w[k].x, acc.x);
            acc.y = fmaf(ak[k], w[k].y, acc.y);
            acc.z = fmaf(ak[k], w[k].z, acc.z);
            acc.w = fmaf(ak[k], w[k].w, acc.w);
        }
        float4 m;
        m.x = fmaxf(xv_cur.x + acc.x, 0.f);
        m.y = fmaxf(xv_cur.y + acc.y, 0.f);
        m.z = fmaxf(xv_cur.z + acc.z, 0.f);
        m.w = fmaxf(xv_cur.w + acc.w, 0.f);
        red_add_v4(&agg[(size_t)d * 128 + lane * 4], m);

        xv_cur = xv_nxt;
        s_nxt = s_n2;
    }
}

// ---------------- 8-cols-per-lane persistent node kernel ----------------
// 128 threads. Block = 64-node tile x 64 cols (blockIdx.y = half).
// Warp: 4 groups of 8 lanes; group handles 4 nodes; lane owns 8 cols (4 u64 acc/node).
// One pack2 feeds 4 fma2 -> ~70% FMA issue density.
template <int K, bool POOL>
__global__ void node_kernel(const float* __restrict__ agg,
                            const float* __restrict__ W,
                            const float* __restrict__ b,
                            const int* __restrict__ batch,
                            float* __restrict__ out,
                            float* __restrict__ out2,
                            int ntiles) {
    extern __shared__ __align__(16) float sm[];
    float* Ws  = sm;               // K * 64 (column half)
    float* ins = sm + K * 64;      // 64 * K
    const int tid = threadIdx.x;
    const int half = blockIdx.y;
    constexpr int K4 = K / 4;

    // stage W column half: Ws[k][c] = W[k][half*64 + c]
    const float4* W4 = reinterpret_cast<const float4*>(W);
    float4* Ws4 = reinterpret_cast<float4*>(Ws);
    for (int i = tid; i < K * 16; i += 128) {
        const int k = i >> 4, c4 = i & 15;
        Ws4[i] = W4[k * 32 + half * 16 + c4];
    }

    const int w    = tid >> 5;        // 0..3
    const int lane = tid & 31;
    const int grp  = lane >> 3;       // 0..3
    const int sub  = lane & 7;        // 0..7 -> cols sub*8..sub*8+7 within half

    // bias: 4 u64 covering cols half*64 + sub*8 .. +7
    u64 bp[4];
#pragma unroll
    for (int j = 0; j < 4; j++)
        bp[j] = reinterpret_cast<const u64*>(b)[half * 32 + sub * 4 + j];

    const float4* a4 = reinterpret_cast<const float4*>(agg);
    float4* in4 = reinterpret_cast<float4*>(ins);
    const u64* Ws8 = reinterpret_cast<const u64*>(Ws);   // row stride = 32 u64

    for (int tile = blockIdx.x; tile < ntiles; tile += gridDim.x) {
        const int base = tile * 64;
        __syncthreads();
        for (int i = tid; i < 64 * K4; i += 128) {
            const int r = i / K4, c = i % K4;
            const int n = base + r;
            in4[i] = (n < N_NODES) ? a4[(size_t)n * K4 + c] : make_float4(0.f, 0.f, 0.f, 0.f);
        }
        __syncthreads();

        // node block for this lane-group: rows w*16 + grp*4 + mm
        const int row0 = w * 16 + grp * 4;
        u64 acc[4][4];
#pragma unroll
        for (int mm = 0; mm < 4; mm++)
#pragma unroll
            for (int j = 0; j < 4; j++) acc[mm][j] = bp[j];

        const float* inbase = ins + row0 * K;
#pragma unroll 1
        for (int k = 0; k < K; k += 4) {
            float4 iv[4];
#pragma unroll
            for (int mm = 0; mm < 4; mm++)
                iv[mm] = *reinterpret_cast<const float4*>(inbase + mm * K + k);
#pragma unroll
            for (int kk = 0; kk < 4; kk++) {
                const u64 w0 = Ws8[(k + kk) * 32 + sub * 4 + 0];
                const u64 w1 = Ws8[(k + kk) * 32 + sub * 4 + 1];
                const u64 w2 = Ws8[(k + kk) * 32 + sub * 4 + 2];
                const u64 w3 = Ws8[(k + kk) * 32 + sub * 4 + 3];
#pragma unroll
                for (int mm = 0; mm < 4; mm++) {
                    const float c = (kk == 0) ? iv[mm].x : (kk == 1) ? iv[mm].y
                                   : (kk == 2) ? iv[mm].z : iv[mm].w;
                    const u64 t = pack2(c, c);
                    acc[mm][0] = fma2(t, w0, acc[mm][0]);
                    acc[mm][1] = fma2(t, w1, acc[mm][1]);
                    acc[mm][2] = fma2(t, w2, acc[mm][2]);
                    acc[mm][3] = fma2(t, w3, acc[mm][3]);
                }
            }
        }

#pragma unroll
        for (int mm = 0; mm < 4; mm++) {
            const int n = base + row0 + mm;
            if (n < N_NODES) {
                const float2 v0 = unpack2(acc[mm][0]);
                const float2 v1 = unpack2(acc[mm][1]);
                const float2 v2 = unpack2(acc[mm][2]);
                const float2 v3 = unpack2(acc[mm][3]);
                float4 r0, r1;
                r0.x = fmaxf(v0.x, 0.f); r0.y = fmaxf(v0.y, 0.f);
                r0.z = fmaxf(v1.x, 0.f); r0.w = fmaxf(v1.y, 0.f);
                r1.x = fmaxf(v2.x, 0.f); r1.y = fmaxf(v2.y, 0.f);
                r1.z = fmaxf(v3.x, 0.f); r1.w = fmaxf(v3.y, 0.f);
                if (POOL) {
                    const int g = batch[n];
                    float* dst = &g_sums[(size_t)g * HIDDEN + half * 64 + sub * 8];
                    red_add_v4(dst, r0);
                    red_add_v4(dst + 4, r1);
                } else {
                    const size_t o = (size_t)n * 32 + half * 16 + sub * 2;   // float4 index
                    reinterpret_cast<float4*>(out)[o]      = r0;
                    reinterpret_cast<float4*>(out)[o + 1]  = r1;
                    reinterpret_cast<float4*>(out2)[o]     = r0;
                    reinterpret_cast<float4*>(out2)[o + 1] = r1;
                }
            }
        }
    }
}

// ---------------- final divide: counts via binary search; self-zeroes g_sums for next replay ----------------
__global__ void div_kernel(const int* __restrict__ batch, float* __restrict__ out) {
    const int g = blockIdx.x;
    const int j = threadIdx.x;
    int lo = 0, hi = N_NODES;
    while (lo < hi) { int mid = (lo + hi) >> 1; if (batch[mid] < g) lo = mid + 1; else hi = mid; }
    const int first = lo;
    lo = first; hi = N_NODES;
    while (lo < hi) { int mid = (lo + hi) >> 1; if (batch[mid] < g + 1) lo = mid + 1; else hi = mid; }
    const float c = fmaxf((float)(lo - first), 1.0f);
    out[g * HIDDEN + j] = g_sums[g * HIDDEN + j] / c;
    g_sums[g * HIDDEN + j] = 0.0f;   // ready for next replay (static init covers first run)
}

// ---------------- launch ----------------
extern "C" void kernel_launch(void* const* d_in, const int* in_sizes, int n_in,
                              void* d_out, int out_size) {
    const float* x     = (const float*)d_in[0];
    const int*   ei    = (const int*)d_in[1];
    const float* ea    = (const float*)d_in[2];
    const int*   batch = (const int*)d_in[3];
    const float *W1 = (const float*)d_in[4],  *b1 = (const float*)d_in[5];
    const float *We1= (const float*)d_in[6],  *be1= (const float*)d_in[7];
    const float *W2 = (const float*)d_in[8],  *b2 = (const float*)d_in[9];
    const float *We2= (const float*)d_in[10], *be2= (const float*)d_in[11];
    const float *W3 = (const float*)d_in[12], *b3 = (const float*)d_in[13];
    const float *We3= (const float*)d_in[14], *be3= (const float*)d_in[15];
    float* out = (float*)d_out;

    void* p;
    cudaGetSymbolAddress(&p, g_agg1); float* agg1 = (float*)p;
    cudaGetSymbolAddress(&p, g_agg2); float* agg2 = (float*)p;
    cudaGetSymbolAddress(&p, g_agg3); float* agg3 = (float*)p;
    cudaGetSymbolAddress(&p, g_h1);   float* h1   = (float*)p;
    cudaGetSymbolAddress(&p, g_h2);   float* h2   = (float*)p;

    const int smem64  = (64  * 64 + 64 * 64)  * 4;  // 32 KB
    const int smem128 = (128 * 64 + 64 * 128) * 4;  // 64 KB
    cudaFuncSetAttribute(node_kernel<64,  false>, cudaFuncAttributeMaxDynamicSharedMemorySize, smem64);
    cudaFuncSetAttribute(node_kernel<128, false>, cudaFuncAttributeMaxDynamicSharedMemorySize, smem128);
    cudaFuncSetAttribute(node_kernel<128, true >, cudaFuncAttributeMaxDynamicSharedMemorySize, smem128);

    const int EDGE_GRID = 152 * 8;
    const int NTILES    = (N_NODES + 63) / 64;          // 782
    const dim3 NGRID64 (444, 2);                        // 888 blocks @128thr, 32KB smem
    const dim3 NGRID128(222, 2);                        // 444 blocks = 3/SM, 1 wave

    init_agg1_kernel<<<1024, 256>>>(x);                                                    // 1
    edge_kernel64<<<EDGE_GRID, 256>>>(x, ei, ea, We1, be1, agg1);                          // 2
    node_kernel<64, false><<<NGRID64, 128, smem64>>>(agg1, W1, b1, nullptr, h1, agg2, NTILES);   // 3
    edge_kernel128<<<EDGE_GRID, 256>>>(h1, ei, ea, We2, be2, agg2);                        // 4
    node_kernel<128, false><<<NGRID128, 128, smem128>>>(agg2, W2, b2, nullptr, h2, agg3, NTILES); // 5
    edge_kernel128<<<EDGE_GRID, 256>>>(h2, ei, ea, We3, be3, agg3);                        // 6
    node_kernel<128, true><<<NGRID128, 128, smem128>>>(agg3, W3, b3, batch, nullptr, nullptr, NTILES); // 7
    div_kernel<<<NUM_GRAPHS, HIDDEN>>>(batch, out);                                        // 8
}

// round 15
// speedup vs baseline: 1.2243x; 1.2243x over previous
#include <cuda_runtime.h>
#include <cstddef>

#define N_NODES   50000
#define N_EDGES   800000
#define IN_CH     64
#define HIDDEN    128
#define NUM_GRAPHS 256

typedef unsigned long long u64;

// ---------------- scratch (static device globals; no allocation) ----------------
__device__ float g_agg1[(size_t)N_NODES * IN_CH];    // init = x,  += edge msgs
__device__ float g_agg2[(size_t)N_NODES * HIDDEN];   // init = h1, += edge msgs
__device__ float g_agg3[(size_t)N_NODES * HIDDEN];   // init = h2, += edge msgs
__device__ float g_h1 [(size_t)N_NODES * HIDDEN];
__device__ float g_h2 [(size_t)N_NODES * HIDDEN];
__device__ float g_sums[(size_t)NUM_GRAPHS * HIDDEN]; // zero at static init; div_kernel re-zeroes

// ---------------- packed f32x2 helpers (sm_103a FFMA2) ----------------
__device__ __forceinline__ u64 pack2(float lo, float hi) {
    u64 r;
    asm("mov.b64 %0, {%1, %2};" : "=l"(r) : "r"(__float_as_uint(lo)), "r"(__float_as_uint(hi)));
    return r;
}
__device__ __forceinline__ u64 fma2(u64 a, u64 b, u64 c) {
    u64 d;
    asm("fma.rn.f32x2 %0, %1, %2, %3;" : "=l"(d) : "l"(a), "l"(b), "l"(c));
    return d;
}
__device__ __forceinline__ float2 unpack2(u64 v) {
    unsigned lo, hi;
    asm("mov.b64 {%0, %1}, %2;" : "=r"(lo), "=r"(hi) : "l"(v));
    return make_float2(__uint_as_float(lo), __uint_as_float(hi));
}

// ---------------- vector reductions (sm_90+) ----------------
__device__ __forceinline__ void red_add_v4(float* addr, float4 v) {
    asm volatile("red.global.add.v4.f32 [%0], {%1,%2,%3,%4};"
                 :: "l"(addr), "f"(v.x), "f"(v.y), "f"(v.z), "f"(v.w) : "memory");
}

// ---------------- init kernel ----------------
__global__ void init_agg1_kernel(const float* __restrict__ x) {   // agg1 = x
    const int n4 = N_NODES * IN_CH / 4;
    const float4* x4 = reinterpret_cast<const float4*>(x);
    for (int i = blockIdx.x * blockDim.x + threadIdx.x; i < n4; i += gridDim.x * blockDim.x)
        reinterpret_cast<float4*>(g_agg1)[i] = x4[i];
}

// ---------------- edge kernel D=64: two edges per warp, depth-2 gather pipeline ----------------
__global__ __launch_bounds__(256, 4)
void edge_kernel64(const float* __restrict__ x,
                   const int* __restrict__ ei,
                   const float* __restrict__ ea,
                   const float* __restrict__ We,
                   const float* __restrict__ be,
                   float* __restrict__ agg) {
    __shared__ __align__(16) float4 Wes4[8 * 16];
    __shared__ __align__(16) float4 bes4[16];
    for (int i = threadIdx.x; i < 8 * 16; i += blockDim.x)
        Wes4[i] = reinterpret_cast<const float4*>(We)[i];
    if (threadIdx.x < 16) bes4[threadIdx.x] = reinterpret_cast<const float4*>(be)[threadIdx.x];
    __syncthreads();

    const int lane = threadIdx.x & 31;
    const int half = lane >> 4;
    const int sub  = lane & 15;
    float4 w[8];
#pragma unroll
    for (int k = 0; k < 8; k++) w[k] = Wes4[k * 16 + sub];
    const float4 bj = bes4[sub];

    const int wid = (blockIdx.x * blockDim.x + threadIdx.x) >> 5;
    const int nw  = (gridDim.x * blockDim.x) >> 5;
    int per = (N_EDGES + nw - 1) / nw;
    per = (per + 1) & ~1;
    const int e0 = wid * per;
    const int e1 = (e0 + per < N_EDGES) ? (e0 + per) : N_EDGES;
    if (e0 >= e1) return;

    const int* __restrict__ srcp = ei;
    const int* __restrict__ dstp = ei + N_EDGES;
    const float4* __restrict__ eav = reinterpret_cast<const float4*>(ea);
    const float4* __restrict__ x4 = reinterpret_cast<const float4*>(x);

    const int last = e1 - 1;
    int ic = e0 + half;       if (ic > last) ic = last;
    int in_ = e0 + 2 + half;  if (in_ > last) in_ = last;
    int s_nxt = srcp[in_];
    float4 xv_cur = x4[(size_t)srcp[ic] * 16 + sub];

    for (int e = e0; e < e1; e += 2) {
        // issue next gather immediately (depth-2 pipeline)
        float4 xv_nxt = x4[(size_t)s_nxt * 16 + sub];
        int i2 = e + 4 + half; if (i2 > last) i2 = last;
        const int s_n2 = srcp[i2];

        // current edge metadata (sequential; L1-resident)
        const float4 a0 = eav[(size_t)ic * 2];
        const float4 a1 = eav[(size_t)ic * 2 + 1];
        const int d = dstp[ic];

        float ak[8] = {a0.x, a0.y, a0.z, a0.w, a1.x, a1.y, a1.z, a1.w};
        float4 acc = bj;
#pragma unroll
        for (int k = 0; k < 8; k++) {
            acc.x = fmaf(ak[k], w[k].x, acc.x);
            acc.y = fmaf(ak[k], w[k].y, acc.y);
            acc.z = fmaf(ak[k], w[k].z, acc.z);
            acc.w = fmaf(ak[k], w[k].w, acc.w);
        }
        float4 m;
        m.x = fmaxf(xv_cur.x + acc.x, 0.f);
        m.y = fmaxf(xv_cur.y + acc.y, 0.f);
        m.z = fmaxf(xv_cur.z + acc.z, 0.f);
        m.w = fmaxf(xv_cur.w + acc.w, 0.f);
        if (e + half < e1)
            red_add_v4(&agg[(size_t)d * 64 + sub * 4], m);

        xv_cur = xv_nxt;
        ic = in_; in_ = i2; s_nxt = s_n2;
    }
}

// ---------------- edge kernel D=128: one edge per warp, depth-2 gather pipeline ----------------
__global__ __launch_bounds__(256, 4)
void edge_kernel128(const float* __restrict__ x,
                    const int* __restrict__ ei,
                    const float* __restrict__ ea,
                    const float* __restrict__ We,
                    const float* __restrict__ be,
                    float* __restrict__ agg) {
    __shared__ __align__(16) float4 Wes4[8 * 32];
    __shared__ __align__(16) float4 bes4[32];
    for (int i = threadIdx.x; i < 8 * 32; i += blockDim.x)
        Wes4[i] = reinterpret_cast<const float4*>(We)[i];
    if (threadIdx.x < 32) bes4[threadIdx.x] = reinterpret_cast<const float4*>(be)[threadIdx.x];
    __syncthreads();

    const int lane = threadIdx.x & 31;
    float4 w[8];
#pragma unroll
    for (int k = 0; k < 8; k++) w[k] = Wes4[k * 32 + lane];
    const float4 bj = bes4[lane];

    const int wid = (blockIdx.x * blockDim.x + threadIdx.x) >> 5;
    const int nw  = (gridDim.x * blockDim.x) >> 5;
    const int per = (N_EDGES + nw - 1) / nw;
    const int e0  = wid * per;
    const int e1  = (e0 + per < N_EDGES) ? (e0 + per) : N_EDGES;
    if (e0 >= e1) return;

    const int* __restrict__ srcp = ei;
    const int* __restrict__ dstp = ei + N_EDGES;
    const float4* __restrict__ eav = reinterpret_cast<const float4*>(ea);
    const float4* __restrict__ x4 = reinterpret_cast<const float4*>(x);

    const int last = e1 - 1;
    int s_nxt = srcp[(e0 + 1 <= last) ? e0 + 1 : last];
    float4 xv_cur = x4[(size_t)srcp[e0] * 32 + lane];

    for (int e = e0; e < e1; ++e) {
        // issue next gather immediately (depth-2 pipeline)
        float4 xv_nxt = x4[(size_t)s_nxt * 32 + lane];
        const int i2 = (e + 2 <= last) ? e + 2 : last;
        const int s_n2 = srcp[i2];

        // current edge metadata (sequential; L1-resident)
        const float4 a0 = eav[(size_t)e * 2];
        const float4 a1 = eav[(size_t)e * 2 + 1];
        const int d = dstp[e];

        float ak[8] = {a0.x, a0.y, a0.z, a0.w, a1.x, a1.y, a1.z, a1.w};
        float4 acc = bj;
#pragma unroll
        for (int k = 0; k < 8; k++) {
            acc.x = fmaf(ak[k], w[k].x, acc.x);
            acc.y = fmaf(ak[k], w[k].y, acc.y);
            acc.z = fmaf(ak[k], w[k].z, acc.z);
            acc.w = fmaf(ak[k], w[k].w, acc.w);
        }
        float4 m;
        m.x = fmaxf(xv_cur.x + acc.x, 0.f);
        m.y = fmaxf(xv_cur.y + acc.y, 0.f);
        m.z = fmaxf(xv_cur.z + acc.z, 0.f);
        m.w = fmaxf(xv_cur.w + acc.w, 0.f);
        red_add_v4(&agg[(size_t)d * 128 + lane * 4], m);

        xv_cur = xv_nxt;
        s_nxt = s_n2;
    }
}

// ---------------- node kernel (staged-smem, R7 proven form): y = relu(agg @ W + b) ----------------
// 256 threads, 64 nodes/block, 8 nodes x 4 cols per thread. FFMA2 inner loop.
template <int K, bool POOL>
__global__ void node_kernel(const float* __restrict__ agg,
                            const float* __restrict__ W,
                            const float* __restrict__ b,
                            const int* __restrict__ batch,
                            float* __restrict__ out,
                            float* __restrict__ out2) {
    extern __shared__ __align__(16) float sm[];
    float* Ws  = sm;               // K * 128
    float* ins = sm + K * 128;     // 64 * K
    const int tid = threadIdx.x;
    constexpr int K4 = K / 4;

    const float4* W4 = reinterpret_cast<const float4*>(W);
    float4* Ws4 = reinterpret_cast<float4*>(Ws);
    for (int i = tid; i < K * 32; i += 256) Ws4[i] = W4[i];

    const int base = blockIdx.x * 64;
    const float4* a4 = reinterpret_cast<const float4*>(agg);
    float4* in4 = reinterpret_cast<float4*>(ins);
    for (int i = tid; i < 64 * K4; i += 256) {
        const int r = i / K4, c = i % K4;
        const int n = base + r;
        in4[i] = (n < N_NODES) ? a4[(size_t)n * K4 + c] : make_float4(0.f, 0.f, 0.f, 0.f);
    }
    __syncthreads();

    const int w = tid >> 5, lane = tid & 31;
    const float4 bj = reinterpret_cast<const float4*>(b)[lane];
    u64 acc0[8], acc1[8];
    const u64 bp0 = pack2(bj.x, bj.y), bp1 = pack2(bj.z, bj.w);
#pragma unroll
    for (int m = 0; m < 8; m++) { acc0[m] = bp0; acc1[m] = bp1; }

    const float* inrow = ins + (w * 8) * K;
#pragma unroll 1
    for (int k = 0; k < K; k += 4) {
        const float4 wv0 = Ws4[(k + 0) * 32 + lane];
        const float4 wv1 = Ws4[(k + 1) * 32 + lane];
        const float4 wv2 = Ws4[(k + 2) * 32 + lane];
        const float4 wv3 = Ws4[(k + 3) * 32 + lane];
        const u64 w00 = pack2(wv0.x, wv0.y), w01 = pack2(wv0.z, wv0.w);
        const u64 w10 = pack2(wv1.x, wv1.y), w11 = pack2(wv1.z, wv1.w);
        const u64 w20 = pack2(wv2.x, wv2.y), w21 = pack2(wv2.z, wv2.w);
        const u64 w30 = pack2(wv3.x, wv3.y), w31 = pack2(wv3.z, wv3.w);
#pragma unroll
        for (int m = 0; m < 8; m++) {
            const float4 iv = *reinterpret_cast<const float4*>(inrow + m * K + k);
            u64 t;
            t = pack2(iv.x, iv.x);
            acc0[m] = fma2(t, w00, acc0[m]);
            acc1[m] = fma2(t, w01, acc1[m]);
            t = pack2(iv.y, iv.y);
            acc0[m] = fma2(t, w10, acc0[m]);
            acc1[m] = fma2(t, w11, acc1[m]);
            t = pack2(iv.z, iv.z);
            acc0[m] = fma2(t, w20, acc0[m]);
            acc1[m] = fma2(t, w21, acc1[m]);
            t = pack2(iv.w, iv.w);
            acc0[m] = fma2(t, w30, acc0[m]);
            acc1[m] = fma2(t, w31, acc1[m]);
        }
    }

#pragma unroll
    for (int m = 0; m < 8; m++) {
        const int n = base + w * 8 + m;
        if (n < N_NODES) {
            const float2 lo = unpack2(acc0[m]);
            const float2 hi = unpack2(acc1[m]);
            float4 r;
            r.x = fmaxf(lo.x, 0.f);
            r.y = fmaxf(lo.y, 0.f);
            r.z = fmaxf(hi.x, 0.f);
            r.w = fmaxf(hi.y, 0.f);
            if (POOL) {
                const int g = batch[n];
                red_add_v4(&g_sums[(size_t)g * HIDDEN + lane * 4], r);
            } else {
                reinterpret_cast<float4*>(out)[(size_t)n * 32 + lane] = r;
                reinterpret_cast<float4*>(out2)[(size_t)n * 32 + lane] = r;  // agg init for next layer
            }
        }
    }
}

// ---------------- final divide: counts via binary search; self-zeroes g_sums for next replay ----------------
__global__ void div_kernel(const int* __restrict__ batch, float* __restrict__ out) {
    const int g = blockIdx.x;
    const int j = threadIdx.x;
    int lo = 0, hi = N_NODES;
    while (lo < hi) { int mid = (lo + hi) >> 1; if (batch[mid] < g) lo = mid + 1; else hi = mid; }
    const int first = lo;
    lo = first; hi = N_NODES;
    while (lo < hi) { int mid = (lo + hi) >> 1; if (batch[mid] < g + 1) lo = mid + 1; else hi = mid; }
    const float c = fmaxf((float)(lo - first), 1.0f);
    out[g * HIDDEN + j] = g_sums[g * HIDDEN + j] / c;
    g_sums[g * HIDDEN + j] = 0.0f;   // invariant: zero at entry of every execution (static init covers run 1)
}

// ---------------- launch ----------------
extern "C" void kernel_launch(void* const* d_in, const int* in_sizes, int n_in,
                              void* d_out, int out_size) {
    const float* x     = (const float*)d_in[0];
    const int*   ei    = (const int*)d_in[1];
    const float* ea    = (const float*)d_in[2];
    const int*   batch = (const int*)d_in[3];
    const float *W1 = (const float*)d_in[4],  *b1 = (const float*)d_in[5];
    const float *We1= (const float*)d_in[6],  *be1= (const float*)d_in[7];
    const float *W2 = (const float*)d_in[8],  *b2 = (const float*)d_in[9];
    const float *We2= (const float*)d_in[10], *be2= (const float*)d_in[11];
    const float *W3 = (const float*)d_in[12], *b3 = (const float*)d_in[13];
    const float *We3= (const float*)d_in[14], *be3= (const float*)d_in[15];
    float* out = (float*)d_out;

    void* p;
    cudaGetSymbolAddress(&p, g_agg1); float* agg1 = (float*)p;
    cudaGetSymbolAddress(&p, g_agg2); float* agg2 = (float*)p;
    cudaGetSymbolAddress(&p, g_agg3); float* agg3 = (float*)p;
    cudaGetSymbolAddress(&p, g_h1);   float* h1   = (float*)p;
    cudaGetSymbolAddress(&p, g_h2);   float* h2   = (float*)p;

    const int smem64  = (64  * 128 + 64 * 64)  * 4;  // 48 KB
    const int smem128 = (128 * 128 + 64 * 128) * 4;  // 96 KB
    cudaFuncSetAttribute(node_kernel<64,  false>, cudaFuncAttributeMaxDynamicSharedMemorySize, smem64);
    cudaFuncSetAttribute(node_kernel<128, false>, cudaFuncAttributeMaxDynamicSharedMemorySize, smem128);
    cudaFuncSetAttribute(node_kernel<128, true >, cudaFuncAttributeMaxDynamicSharedMemorySize, smem128);

    const int EDGE_GRID = 152 * 8;                 // measured-best grid (R7)
    const int NODE_GRID = (N_NODES + 63) / 64;

    init_agg1_kernel<<<1024, 256>>>(x);                                                    // 1
    edge_kernel64<<<EDGE_GRID, 256>>>(x, ei, ea, We1, be1, agg1);                          // 2
    node_kernel<64, false><<<NODE_GRID, 256, smem64>>>(agg1, W1, b1, nullptr, h1, agg2);   // 3
    edge_kernel128<<<EDGE_GRID, 256>>>(h1, ei, ea, We2, be2, agg2);                        // 4
    node_kernel<128, false><<<NODE_GRID, 256, smem128>>>(agg2, W2, b2, nullptr, h2, agg3); // 5
    edge_kernel128<<<EDGE_GRID, 256>>>(h2, ei, ea, We3, be3, agg3);                        // 6
    node_kernel<128, true><<<NODE_GRID, 256, smem128>>>(agg3, W3, b3, batch, nullptr, nullptr); // 7
    div_kernel<<<NUM_GRAPHS, HIDDEN>>>(batch, out);                                        // 8
}

// round 17
// speedup vs baseline: 1.2373x; 1.0106x over previous
#include <cuda_runtime.h>
#include <cstddef>

#define N_NODES   50000
#define N_EDGES   800000
#define IN_CH     64
#define HIDDEN    128
#define NUM_GRAPHS 256

typedef unsigned long long u64;

// ---------------- scratch (static device globals; no allocation) ----------------
__device__ float g_agg1[(size_t)N_NODES * IN_CH];    // init = x,  += edge msgs
__device__ float g_agg2[(size_t)N_NODES * HIDDEN];   // init = h1, += edge msgs
__device__ float g_agg3[(size_t)N_NODES * HIDDEN];   // init = h2, += edge msgs
__device__ float g_h1 [(size_t)N_NODES * HIDDEN];
__device__ float g_h2 [(size_t)N_NODES * HIDDEN];
__device__ float g_sums[(size_t)NUM_GRAPHS * HIDDEN]; // zero at static init; div_kernel re-zeroes

// ---------------- packed f32x2 helpers (sm_103a FFMA2) ----------------
__device__ __forceinline__ u64 pack2(float lo, float hi) {
    u64 r;
    asm("mov.b64 %0, {%1, %2};" : "=l"(r) : "r"(__float_as_uint(lo)), "r"(__float_as_uint(hi)));
    return r;
}
__device__ __forceinline__ u64 fma2(u64 a, u64 b, u64 c) {
    u64 d;
    asm("fma.rn.f32x2 %0, %1, %2, %3;" : "=l"(d) : "l"(a), "l"(b), "l"(c));
    return d;
}
__device__ __forceinline__ float2 unpack2(u64 v) {
    unsigned lo, hi;
    asm("mov.b64 {%0, %1}, %2;" : "=r"(lo), "=r"(hi) : "l"(v));
    return make_float2(__uint_as_float(lo), __uint_as_float(hi));
}

// ---------------- vector reductions (sm_90+) ----------------
__device__ __forceinline__ void red_add_v4(float* addr, float4 v) {
    asm volatile("red.global.add.v4.f32 [%0], {%1,%2,%3,%4};"
                 :: "l"(addr), "f"(v.x), "f"(v.y), "f"(v.z), "f"(v.w) : "memory");
}

// ---------------- init kernel ----------------
__global__ void init_agg1_kernel(const float* __restrict__ x) {   // agg1 = x
    const int n4 = N_NODES * IN_CH / 4;
    const float4* x4 = reinterpret_cast<const float4*>(x);
    for (int i = blockIdx.x * blockDim.x + threadIdx.x; i < n4; i += gridDim.x * blockDim.x)
        reinterpret_cast<float4*>(g_agg1)[i] = x4[i];
}

// ---------------- edge kernel D=64: two edges per warp, depth-2 gather pipeline ----------------
__global__ __launch_bounds__(256, 4)
void edge_kernel64(const float* __restrict__ x,
                   const int* __restrict__ ei,
                   const float* __restrict__ ea,
                   const float* __restrict__ We,
                   const float* __restrict__ be,
                   float* __restrict__ agg) {
    __shared__ __align__(16) float4 Wes4[8 * 16];
    __shared__ __align__(16) float4 bes4[16];
    for (int i = threadIdx.x; i < 8 * 16; i += blockDim.x)
        Wes4[i] = reinterpret_cast<const float4*>(We)[i];
    if (threadIdx.x < 16) bes4[threadIdx.x] = reinterpret_cast<const float4*>(be)[threadIdx.x];
    __syncthreads();

    const int lane = threadIdx.x & 31;
    const int half = lane >> 4;
    const int sub  = lane & 15;
    float4 w[8];
#pragma unroll
    for (int k = 0; k < 8; k++) w[k] = Wes4[k * 16 + sub];
    const float4 bj = bes4[sub];

    const int wid = (blockIdx.x * blockDim.x + threadIdx.x) >> 5;
    const int nw  = (gridDim.x * blockDim.x) >> 5;
    int per = (N_EDGES + nw - 1) / nw;
    per = (per + 1) & ~1;
    const int e0 = wid * per;
    const int e1 = (e0 + per < N_EDGES) ? (e0 + per) : N_EDGES;
    if (e0 >= e1) return;

    const int* __restrict__ srcp = ei;
    const int* __restrict__ dstp = ei + N_EDGES;
    const float4* __restrict__ eav = reinterpret_cast<const float4*>(ea);
    const float4* __restrict__ x4 = reinterpret_cast<const float4*>(x);

    const int last = e1 - 1;
    int ic = e0 + half;       if (ic > last) ic = last;
    int in_ = e0 + 2 + half;  if (in_ > last) in_ = last;
    int s_nxt = srcp[in_];
    float4 xv_cur = x4[(size_t)srcp[ic] * 16 + sub];

    for (int e = e0; e < e1; e += 2) {
        // issue next gather immediately (depth-2 pipeline)
        float4 xv_nxt = x4[(size_t)s_nxt * 16 + sub];
        int i2 = e + 4 + half; if (i2 > last) i2 = last;
        const int s_n2 = srcp[i2];

        // current edge metadata (sequential; L1-resident)
        const float4 a0 = eav[(size_t)ic * 2];
        const float4 a1 = eav[(size_t)ic * 2 + 1];
        const int d = dstp[ic];

        float ak[8] = {a0.x, a0.y, a0.z, a0.w, a1.x, a1.y, a1.z, a1.w};
        float4 acc = bj;
#pragma unroll
        for (int k = 0; k < 8; k++) {
            acc.x = fmaf(ak[k], w[k].x, acc.x);
            acc.y = fmaf(ak[k], w[k].y, acc.y);
            acc.z = fmaf(ak[k], w[k].z, acc.z);
            acc.w = fmaf(ak[k], w[k].w, acc.w);
        }
        float4 m;
        m.x = fmaxf(xv_cur.x + acc.x, 0.f);
        m.y = fmaxf(xv_cur.y + acc.y, 0.f);
        m.z = fmaxf(xv_cur.z + acc.z, 0.f);
        m.w = fmaxf(xv_cur.w + acc.w, 0.f);
        if (e + half < e1)
            red_add_v4(&agg[(size_t)d * 64 + sub * 4], m);

        xv_cur = xv_nxt;
        ic = in_; in_ = i2; s_nxt = s_n2;
    }
}

// ---------------- edge kernel D=128: one edge per warp, depth-2 gather pipeline ----------------
__global__ __launch_bounds__(256, 4)
void edge_kernel128(const float* __restrict__ x,
                    const int* __restrict__ ei,
                    const float* __restrict__ ea,
                    const float* __restrict__ We,
                    const float* __restrict__ be,
                    float* __restrict__ agg) {
    __shared__ __align__(16) float4 Wes4[8 * 32];
    __shared__ __align__(16) float4 bes4[32];
    for (int i = threadIdx.x; i < 8 * 32; i += blockDim.x)
        Wes4[i] = reinterpret_cast<const float4*>(We)[i];
    if (threadIdx.x < 32) bes4[threadIdx.x] = reinterpret_cast<const float4*>(be)[threadIdx.x];
    __syncthreads();

    const int lane = threadIdx.x & 31;
    float4 w[8];
#pragma unroll
    for (int k = 0; k < 8; k++) w[k] = Wes4[k * 32 + lane];
    const float4 bj = bes4[lane];

    const int wid = (blockIdx.x * blockDim.x + threadIdx.x) >> 5;
    const int nw  = (gridDim.x * blockDim.x) >> 5;
    const int per = (N_EDGES + nw - 1) / nw;
    const int e0  = wid * per;
    const int e1  = (e0 + per < N_EDGES) ? (e0 + per) : N_EDGES;
    if (e0 >= e1) return;

    const int* __restrict__ srcp = ei;
    const int* __restrict__ dstp = ei + N_EDGES;
    const float4* __restrict__ eav = reinterpret_cast<const float4*>(ea);
    const float4* __restrict__ x4 = reinterpret_cast<const float4*>(x);

    const int last = e1 - 1;
    int s_nxt = srcp[(e0 + 1 <= last) ? e0 + 1 : last];
    float4 xv_cur = x4[(size_t)srcp[e0] * 32 + lane];

    for (int e = e0; e < e1; ++e) {
        // issue next gather immediately (depth-2 pipeline)
        float4 xv_nxt = x4[(size_t)s_nxt * 32 + lane];
        const int i2 = (e + 2 <= last) ? e + 2 : last;
        const int s_n2 = srcp[i2];

        // current edge metadata (sequential; L1-resident)
        const float4 a0 = eav[(size_t)e * 2];
        const float4 a1 = eav[(size_t)e * 2 + 1];
        const int d = dstp[e];

        float ak[8] = {a0.x, a0.y, a0.z, a0.w, a1.x, a1.y, a1.z, a1.w};
        float4 acc = bj;
#pragma unroll
        for (int k = 0; k < 8; k++) {
            acc.x = fmaf(ak[k], w[k].x, acc.x);
            acc.y = fmaf(ak[k], w[k].y, acc.y);
            acc.z = fmaf(ak[k], w[k].z, acc.z);
            acc.w = fmaf(ak[k], w[k].w, acc.w);
        }
        float4 m;
        m.x = fmaxf(xv_cur.x + acc.x, 0.f);
        m.y = fmaxf(xv_cur.y + acc.y, 0.f);
        m.z = fmaxf(xv_cur.z + acc.z, 0.f);
        m.w = fmaxf(xv_cur.w + acc.w, 0.f);
        red_add_v4(&agg[(size_t)d * 128 + lane * 4], m);

        xv_cur = xv_nxt;
        s_nxt = s_n2;
    }
}

// ---------------- node kernel (staged-smem): y = relu(agg @ W + b) ----------------
// 256 threads, 64 nodes/block, 8 nodes x 4 cols per thread. FFMA2 inner loop,
// k-loop unrolled x2 so two k4 iterations' independent LDS overlap.
template <int K, bool POOL>
__global__ void node_kernel(const float* __restrict__ agg,
                            const float* __restrict__ W,
                            const float* __restrict__ b,
                            const int* __restrict__ batch,
                            float* __restrict__ out,
                            float* __restrict__ out2) {
    extern __shared__ __align__(16) float sm[];
    float* Ws  = sm;               // K * 128
    float* ins = sm + K * 128;     // 64 * K
    const int tid = threadIdx.x;
    constexpr int K4 = K / 4;

    const float4* W4 = reinterpret_cast<const float4*>(W);
    float4* Ws4 = reinterpret_cast<float4*>(Ws);
    for (int i = tid; i < K * 32; i += 256) Ws4[i] = W4[i];

    const int base = blockIdx.x * 64;
    const float4* a4 = reinterpret_cast<const float4*>(agg);
    float4* in4 = reinterpret_cast<float4*>(ins);
    for (int i = tid; i < 64 * K4; i += 256) {
        const int r = i / K4, c = i % K4;
        const int n = base + r;
        in4[i] = (n < N_NODES) ? a4[(size_t)n * K4 + c] : make_float4(0.f, 0.f, 0.f, 0.f);
    }
    __syncthreads();

    const int w = tid >> 5, lane = tid & 31;
    const float4 bj = reinterpret_cast<const float4*>(b)[lane];
    u64 acc0[8], acc1[8];
    const u64 bp0 = pack2(bj.x, bj.y), bp1 = pack2(bj.z, bj.w);
#pragma unroll
    for (int m = 0; m < 8; m++) { acc0[m] = bp0; acc1[m] = bp1; }

    const float* inrow = ins + (w * 8) * K;
#pragma unroll 2
    for (int k = 0; k < K; k += 4) {
        const float4 wv0 = Ws4[(k + 0) * 32 + lane];
        const float4 wv1 = Ws4[(k + 1) * 32 + lane];
        const float4 wv2 = Ws4[(k + 2) * 32 + lane];
        const float4 wv3 = Ws4[(k + 3) * 32 + lane];
        const u64 w00 = pack2(wv0.x, wv0.y), w01 = pack2(wv0.z, wv0.w);
        const u64 w10 = pack2(wv1.x, wv1.y), w11 = pack2(wv1.z, wv1.w);
        const u64 w20 = pack2(wv2.x, wv2.y), w21 = pack2(wv2.z, wv2.w);
        const u64 w30 = pack2(wv3.x, wv3.y), w31 = pack2(wv3.z, wv3.w);
#pragma unroll
        for (int m = 0; m < 8; m++) {
            const float4 iv = *reinterpret_cast<const float4*>(inrow + m * K + k);
            u64 t;
            t = pack2(iv.x, iv.x);
            acc0[m] = fma2(t, w00, acc0[m]);
            acc1[m] = fma2(t, w01, acc1[m]);
            t = pack2(iv.y, iv.y);
            acc0[m] = fma2(t, w10, acc0[m]);
            acc1[m] = fma2(t, w11, acc1[m]);
            t = pack2(iv.z, iv.z);
            acc0[m] = fma2(t, w20, acc0[m]);
            acc1[m] = fma2(t, w21, acc1[m]);
            t = pack2(iv.w, iv.w);
            acc0[m] = fma2(t, w30, acc0[m]);
            acc1[m] = fma2(t, w31, acc1[m]);
        }
    }

#pragma unroll
    for (int m = 0; m < 8; m++) {
        const int n = base + w * 8 + m;
        if (n < N_NODES) {
            const float2 lo = unpack2(acc0[m]);
            const float2 hi = unpack2(acc1[m]);
            float4 r;
            r.x = fmaxf(lo.x, 0.f);
            r.y = fmaxf(lo.y, 0.f);
            r.z = fmaxf(hi.x, 0.f);
            r.w = fmaxf(hi.y, 0.f);
            if (POOL) {
                const int g = batch[n];
                red_add_v4(&g_sums[(size_t)g * HIDDEN + lane * 4], r);
            } else {
                reinterpret_cast<float4*>(out)[(size_t)n * 32 + lane] = r;
                reinterpret_cast<float4*>(out2)[(size_t)n * 32 + lane] = r;  // agg init for next layer
            }
        }
    }
}

// ---------------- final divide: counts via binary search; self-zeroes g_sums for next replay ----------------
__global__ void div_kernel(const int* __restrict__ batch, float* __restrict__ out) {
    const int g = blockIdx.x;
    const int j = threadIdx.x;
    int lo = 0, hi = N_NODES;
    while (lo < hi) { int mid = (lo + hi) >> 1; if (batch[mid] < g) lo = mid + 1; else hi = mid; }
    const int first = lo;
    lo = first; hi = N_NODES;
    while (lo < hi) { int mid = (lo + hi) >> 1; if (batch[mid] < g + 1) lo = mid + 1; else hi = mid; }
    const float c = fmaxf((float)(lo - first), 1.0f);
    out[g * HIDDEN + j] = g_sums[g * HIDDEN + j] / c;
    g_sums[g * HIDDEN + j] = 0.0f;   // invariant: zero at entry of every execution (static init covers run 1)
}

// ---------------- launch ----------------
extern "C" void kernel_launch(void* const* d_in, const int* in_sizes, int n_in,
                              void* d_out, int out_size) {
    const float* x     = (const float*)d_in[0];
    const int*   ei    = (const int*)d_in[1];
    const float* ea    = (const float*)d_in[2];
    const int*   batch = (const int*)d_in[3];
    const float *W1 = (const float*)d_in[4],  *b1 = (const float*)d_in[5];
    const float *We1= (const float*)d_in[6],  *be1= (const float*)d_in[7];
    const float *W2 = (const float*)d_in[8],  *b2 = (const float*)d_in[9];
    const float *We2= (const float*)d_in[10], *be2= (const float*)d_in[11];
    const float *W3 = (const float*)d_in[12], *b3 = (const float*)d_in[13];
    const float *We3= (const float*)d_in[14], *be3= (const float*)d_in[15];
    float* out = (float*)d_out;

    void* p;
    cudaGetSymbolAddress(&p, g_agg1); float* agg1 = (float*)p;
    cudaGetSymbolAddress(&p, g_agg2); float* agg2 = (float*)p;
    cudaGetSymbolAddress(&p, g_agg3); float* agg3 = (float*)p;
    cudaGetSymbolAddress(&p, g_h1);   float* h1   = (float*)p;
    cudaGetSymbolAddress(&p, g_h2);   float* h2   = (float*)p;

    const int smem64  = (64  * 128 + 64 * 64)  * 4;  // 48 KB
    const int smem128 = (128 * 128 + 64 * 128) * 4;  // 96 KB
    cudaFuncSetAttribute(node_kernel<64,  false>, cudaFuncAttributeMaxDynamicSharedMemorySize, smem64);
    cudaFuncSetAttribute(node_kernel<128, false>, cudaFuncAttributeMaxDynamicSharedMemorySize, smem128);
    cudaFuncSetAttribute(node_kernel<128, true >, cudaFuncAttributeMaxDynamicSharedMemorySize, smem128);

    const int EDGE_GRID = 152 * 8;                 // measured-best grid
    const int NODE_GRID = (N_NODES + 63) / 64;

    init_agg1_kernel<<<1024, 256>>>(x);                                                    // 1
    edge_kernel64<<<EDGE_GRID, 256>>>(x, ei, ea, We1, be1, agg1);                          // 2
    node_kernel<64, false><<<NODE_GRID, 256, smem64>>>(agg1, W1, b1, nullptr, h1, agg2);   // 3
    edge_kernel128<<<EDGE_GRID, 256>>>(h1, ei, ea, We2, be2, agg2);                        // 4
    node_kernel<128, false><<<NODE_GRID, 256, smem128>>>(agg2, W2, b2, nullptr, h2, agg3); // 5
    edge_kernel128<<<EDGE_GRID, 256>>>(h2, ei, ea, We3, be3, agg3);                        // 6
    node_kernel<128, true><<<NODE_GRID, 256, smem128>>>(agg3, W3, b3, batch, nullptr, nullptr); // 7
    div_kernel<<<NUM_GRAPHS, HIDDEN>>>(batch, out);                                        // 8
}